// round 6
// baseline (speedup 1.0000x reference)
#include <cuda_runtime.h>
#include <cuda_bf16.h>

// Problem constants (fixed by the reference)
#define PB 16
#define PC 128
#define PK 128
#define PD 256
#define BCD (PB*PC*PD)   // 524288
#define BKD (PB*PK*PD)   // 524288
#define CD  (PC*PD)      // 32768
#define KD  (PK*PD)      // 32768

// Scratch (no allocations allowed -> __device__ globals)
__device__ float g_raw0[BCD];
__device__ float g_raw1[BKD];
__device__ float g_s0[BCD];
__device__ float g_s1[BKD];
__device__ float g_t1[BKD];     // kc * sigmoid(g1)
__device__ float g_scale[256];  // [0..127] bn0, [128..255] bn1
__device__ float g_shift[256];

// ---------------------------------------------------------------------------
// Dual GEMM: z=0 -> raw0 = q @ W0^T ; z=1 -> raw1 = kc @ W1^T
// ---------------------------------------------------------------------------
__global__ void gemm_dual(const float* __restrict__ q, const float* __restrict__ kc,
                          const float* __restrict__ W0, const float* __restrict__ W1,
                          float* __restrict__ o0, float* __restrict__ o1)
{
    const float* A  = blockIdx.z ? kc : q;
    const float* Bm = blockIdx.z ? W1 : W0;
    float*       C  = blockIdx.z ? o1 : o0;

    __shared__ __align__(16) float As[32][68];
    __shared__ __align__(16) float Bs[32][68];

    const int tid = threadIdx.x;
    const int tx = tid & 15;
    const int ty = tid >> 4;
    const int m0 = blockIdx.y * 64;
    const int n0 = blockIdx.x * 64;

    const int lr  = tid >> 2;
    const int lcb = (tid & 3) * 8;

    const float* Ap = A  + (long)(m0 + lr) * 256 + lcb;
    const float* Bp = Bm + (long)(n0 + lr) * 256 + lcb;

    float acc[4][4];
#pragma unroll
    for (int i = 0; i < 4; i++)
#pragma unroll
        for (int j = 0; j < 4; j++) acc[i][j] = 0.f;

    float4 a0 = *(const float4*)Ap;
    float4 a1 = *(const float4*)(Ap + 4);
    float4 b0 = *(const float4*)Bp;
    float4 b1 = *(const float4*)(Bp + 4);

    for (int k0 = 0; k0 < 256; k0 += 32) {
        As[lcb+0][lr] = a0.x; As[lcb+1][lr] = a0.y; As[lcb+2][lr] = a0.z; As[lcb+3][lr] = a0.w;
        As[lcb+4][lr] = a1.x; As[lcb+5][lr] = a1.y; As[lcb+6][lr] = a1.z; As[lcb+7][lr] = a1.w;
        Bs[lcb+0][lr] = b0.x; Bs[lcb+1][lr] = b0.y; Bs[lcb+2][lr] = b0.z; Bs[lcb+3][lr] = b0.w;
        Bs[lcb+4][lr] = b1.x; Bs[lcb+5][lr] = b1.y; Bs[lcb+6][lr] = b1.z; Bs[lcb+7][lr] = b1.w;
        __syncthreads();

        if (k0 + 32 < 256) {
            a0 = *(const float4*)(Ap + k0 + 32);
            a1 = *(const float4*)(Ap + k0 + 36);
            b0 = *(const float4*)(Bp + k0 + 32);
            b1 = *(const float4*)(Bp + k0 + 36);
        }

#pragma unroll
        for (int kq = 0; kq < 32; kq++) {
            float4 av = *(const float4*)&As[kq][ty * 4];
            float4 bv = *(const float4*)&Bs[kq][tx * 4];
            acc[0][0] += av.x*bv.x; acc[0][1] += av.x*bv.y; acc[0][2] += av.x*bv.z; acc[0][3] += av.x*bv.w;
            acc[1][0] += av.y*bv.x; acc[1][1] += av.y*bv.y; acc[1][2] += av.y*bv.z; acc[1][3] += av.y*bv.w;
            acc[2][0] += av.z*bv.x; acc[2][1] += av.z*bv.y; acc[2][2] += av.z*bv.z; acc[2][3] += av.z*bv.w;
            acc[3][0] += av.w*bv.x; acc[3][1] += av.w*bv.y; acc[3][2] += av.w*bv.z; acc[3][3] += av.w*bv.w;
        }
        __syncthreads();
    }

#pragma unroll
    for (int i = 0; i < 4; i++) {
        float4 r = make_float4(acc[i][0], acc[i][1], acc[i][2], acc[i][3]);
        *(float4*)&C[(long)(m0 + ty*4 + i) * 256 + n0 + tx*4] = r;
    }
}

// ---------------------------------------------------------------------------
// BatchNorm stats: 1 block per channel (256 blocks)
// ---------------------------------------------------------------------------
__global__ void bn_stats(const float* __restrict__ gamma0, const float* __restrict__ beta0,
                         const float* __restrict__ gamma1, const float* __restrict__ beta1)
{
    const int cb = blockIdx.x;
    const int c  = cb & 127;
    const float* src = (cb < 128) ? g_raw0 : g_raw1;
    const int t = threadIdx.x;

    float s = 0.f, ss = 0.f;
    const float* p = src + c * PD + t;
#pragma unroll
    for (int b = 0; b < PB; b++) {
        float v = p[b * CD];
        s += v; ss += v * v;
    }

    __shared__ float sh[256], sh2[256];
    sh[t] = s; sh2[t] = ss;
    __syncthreads();
    for (int o = 128; o > 0; o >>= 1) {
        if (t < o) { sh[t] += sh[t + o]; sh2[t] += sh2[t + o]; }
        __syncthreads();
    }
    if (t == 0) {
        const float inv_n = 1.f / 4096.f;
        float mean = sh[0] * inv_n;
        float var  = sh2[0] * inv_n - mean * mean;
        float g  = (cb < 128) ? gamma0[c] : gamma1[c];
        float be = (cb < 128) ? beta0[c]  : beta1[c];
        float sc = g * rsqrtf(var + 1e-5f);
        g_scale[cb] = sc;
        g_shift[cb] = be - mean * sc;
    }
}

// ---------------------------------------------------------------------------
// Apply BN + sigmoid (float4): s0, s1, and t1 = kc * s1
// ---------------------------------------------------------------------------
__global__ void bn_apply(const float* __restrict__ kc)
{
    const int i = blockIdx.x * blockDim.x + threadIdx.x;
    if (i >= BCD / 4) return;
    const int ch = (i >> 6) & 127;

    {
        const float sc = g_scale[ch], sf = g_shift[ch];
        float4 v = ((const float4*)g_raw0)[i];
        float4 r;
        r.x = 1.f / (1.f + __expf(-(v.x * sc + sf)));
        r.y = 1.f / (1.f + __expf(-(v.y * sc + sf)));
        r.z = 1.f / (1.f + __expf(-(v.z * sc + sf)));
        r.w = 1.f / (1.f + __expf(-(v.w * sc + sf)));
        ((float4*)g_s0)[i] = r;
    }
    {
        const float sc = g_scale[128 + ch], sf = g_shift[128 + ch];
        float4 v = ((const float4*)g_raw1)[i];
        float4 kv = ((const float4*)kc)[i];
        float4 r, t;
        r.x = 1.f / (1.f + __expf(-(v.x * sc + sf)));
        r.y = 1.f / (1.f + __expf(-(v.y * sc + sf)));
        r.z = 1.f / (1.f + __expf(-(v.z * sc + sf)));
        r.w = 1.f / (1.f + __expf(-(v.w * sc + sf)));
        t.x = kv.x * r.x; t.y = kv.y * r.y; t.z = kv.z * r.z; t.w = kv.w * r.w;
        ((float4*)g_s1)[i] = r;
        ((float4*)g_t1)[i] = t;
    }
}

// ---------------------------------------------------------------------------
// Heterogeneous fused kernel (single wave: launch_bounds(256,4) -> <=64 regs,
// 4 CTAs/SM, 592 slots >= 576 blocks):
//   blocks [0, 64): out3 GEMM  -- out3[b] = (1/256) * s0[b] @ s1[b]^T
//   blocks [64, 576): stream   -- out2 = mask*t1*s0 (__stcs) + out1 k-sum/tanh
// ---------------------------------------------------------------------------
__global__ void __launch_bounds__(256, 4) fused_kernel(
    const int* __restrict__ cmask, const int* __restrict__ kmask,
    const int* __restrict__ klen,
    float* __restrict__ out1, float* __restrict__ out2, float* __restrict__ out3)
{
    const int tid = threadIdx.x;

    if (blockIdx.x < 64) {
        // ---------------- out3 GEMM role ----------------
        const int idx  = blockIdx.x;
        const int bz   = idx >> 2;
        const int tile = idx & 3;
        const int m0 = (tile >> 1) * 64;
        const int n0 = (tile & 1) * 64;

        const float* Ab = g_s0 + (long)bz * CD;
        const float* Bb = g_s1 + (long)bz * KD;
        float*       Cb = out3 + (long)bz * PC * PK;

        __shared__ __align__(16) float As[16][68];
        __shared__ __align__(16) float Bs[16][68];

        const int tx = tid & 15;
        const int ty = tid >> 4;
        const int kk = tid & 15;
        const int r  = tid >> 4;

        float acc[4][4];
#pragma unroll
        for (int i = 0; i < 4; i++)
#pragma unroll
            for (int j = 0; j < 4; j++) acc[i][j] = 0.f;

        for (int k0 = 0; k0 < 256; k0 += 16) {
#pragma unroll
            for (int p = 0; p < 4; p++) {
                As[kk][r + p*16] = Ab[(long)(m0 + r + p*16) * 256 + k0 + kk];
                Bs[kk][r + p*16] = Bb[(long)(n0 + r + p*16) * 256 + k0 + kk];
            }
            __syncthreads();
#pragma unroll
            for (int kq = 0; kq < 16; kq++) {
                float4 av = *(const float4*)&As[kq][ty * 4];
                float4 bv = *(const float4*)&Bs[kq][tx * 4];
                acc[0][0] += av.x*bv.x; acc[0][1] += av.x*bv.y; acc[0][2] += av.x*bv.z; acc[0][3] += av.x*bv.w;
                acc[1][0] += av.y*bv.x; acc[1][1] += av.y*bv.y; acc[1][2] += av.y*bv.z; acc[1][3] += av.y*bv.w;
                acc[2][0] += av.z*bv.x; acc[2][1] += av.z*bv.y; acc[2][2] += av.z*bv.z; acc[2][3] += av.z*bv.w;
                acc[3][0] += av.w*bv.x; acc[3][1] += av.w*bv.y; acc[3][2] += av.w*bv.z; acc[3][3] += av.w*bv.w;
            }
            __syncthreads();
        }

#pragma unroll
        for (int i = 0; i < 4; i++) {
            const long row = m0 + ty*4 + i;
#pragma unroll
            for (int j = 0; j < 4; j++)
                Cb[row * PK + n0 + tx*4 + j] = acc[i][j] * (1.f / 256.f);
        }
        return;
    }

    // ---------------- stream role ----------------
    const int sb = blockIdx.x - 64;
    const int c0 = (sb & 31) * 4;
    const int b  = sb >> 5;
    const int dq = tid & 63;
    const int ks = tid >> 6;

    __shared__ int skm[PK];
    if (tid < PK) skm[tid] = kmask[b * PK + tid];

    float4 s0d[4];
    int cm[4];
#pragma unroll
    for (int j = 0; j < 4; j++) {
        s0d[j] = ((const float4*)(g_s0 + (long)(b * PC + c0 + j) * PD))[dq];
        cm[j]  = cmask[b * PC + c0 + j];
    }
    const int anyc = cm[0] | cm[1] | cm[2] | cm[3];
    const float invlen = 1.f / (float)klen[b];
    const float4* t1v = (const float4*)(g_t1 + (long)b * KD) + dq;
    float4* o2 = (float4*)(out2 + (long)(b * PC + c0) * KD) + dq;
    __syncthreads();

    float4 acc[4];
#pragma unroll
    for (int j = 0; j < 4; j++) acc[j] = make_float4(0.f, 0.f, 0.f, 0.f);

    for (int k = ks; k < PK; k += 4) {
        const int m = skm[k] & anyc;
        float4 t = make_float4(0.f, 0.f, 0.f, 0.f);
        if (m) t = t1v[k * 64];
#pragma unroll
        for (int j = 0; j < 4; j++) {
            float4 v = make_float4(0.f, 0.f, 0.f, 0.f);
            if (m & cm[j]) {
                v.x = t.x * s0d[j].x; v.y = t.y * s0d[j].y;
                v.z = t.z * s0d[j].z; v.w = t.w * s0d[j].w;
                acc[j].x += v.x; acc[j].y += v.y; acc[j].z += v.z; acc[j].w += v.w;
            }
            __stcs(&o2[(long)j * (KD / 4) + k * 64], v);
        }
    }

    __shared__ float4 sh[256];
#pragma unroll
    for (int j = 0; j < 4; j++) {
        __syncthreads();
        sh[tid] = acc[j];
        __syncthreads();
        if (tid < 64) {
            float4 a = sh[tid], b4 = sh[tid + 64], c4 = sh[tid + 128], d4 = sh[tid + 192];
            float4 r;
            r.x = tanhf((a.x + b4.x + c4.x + d4.x) * invlen);
            r.y = tanhf((a.y + b4.y + c4.y + d4.y) * invlen);
            r.z = tanhf((a.z + b4.z + c4.z + d4.z) * invlen);
            r.w = tanhf((a.w + b4.w + c4.w + d4.w) * invlen);
            ((float4*)(out1 + (long)(b * PC + c0 + j) * PD))[tid] = r;
        }
    }
}

// ---------------------------------------------------------------------------
extern "C" void kernel_launch(void* const* d_in, const int* in_sizes, int n_in,
                              void* d_out, int out_size)
{
    const float* q      = (const float*)d_in[0];   // (B,C,D)
    const float* kc     = (const float*)d_in[1];   // (B,K,D)
    const float* W0     = (const float*)d_in[2];   // (D,D)
    const float* W1     = (const float*)d_in[3];   // (D,D)
    const float* bn0_g  = (const float*)d_in[4];
    const float* bn0_b  = (const float*)d_in[5];
    const float* bn1_g  = (const float*)d_in[6];
    const float* bn1_b  = (const float*)d_in[7];
    const int*   cmask  = (const int*)d_in[8];     // (B,C)
    const int*   kmask  = (const int*)d_in[9];     // (B,K)
    const int*   klen   = (const int*)d_in[10];    // (B,)

    float* out  = (float*)d_out;
    float* out1 = out;                                   // (B,C,D)
    float* out2 = out + (long)BCD;                       // (B,C,K,D)
    float* out3 = out + (long)BCD + (long)PB*PC*PK*PD;   // (B,C,K)

    float *raw0, *raw1;
    cudaGetSymbolAddress((void**)&raw0, g_raw0);
    cudaGetSymbolAddress((void**)&raw1, g_raw1);

    // 1) raw0 = q @ W0^T ; raw1 = kc @ W1^T
    gemm_dual<<<dim3(4, 32, 2), 256>>>(q, kc, W0, W1, raw0, raw1);

    // 2) BN stats -> scale/shift
    bn_stats<<<256, 256>>>(bn0_g, bn0_b, bn1_g, bn1_b);

    // 3) sigmoid gates + t1 (float4)
    bn_apply<<<BCD / 4 / 256, 256>>>(kc);

    // 4) heterogeneous fused: out3 GEMM (64 blocks) + stream (512 blocks), 1 wave
    fused_kernel<<<64 + 512, 256>>>(cmask, kmask, klen, out1, out2, out3);
}

// round 7
// speedup vs baseline: 1.1683x; 1.1683x over previous
#include <cuda_runtime.h>
#include <cuda_bf16.h>

// Problem constants (fixed by the reference)
#define PB 16
#define PC 128
#define PK 128
#define PD 256
#define BCD (PB*PC*PD)   // 524288
#define BKD (PB*PK*PD)   // 524288
#define CD  (PC*PD)      // 32768
#define KD  (PK*PD)      // 32768

// Scratch (no allocations allowed -> __device__ globals)
__device__ float g_raw0[BCD];
__device__ float g_raw1[BKD];
__device__ float g_s0[BCD];
__device__ float g_s1[BKD];
__device__ float g_t1[BKD];     // kc * sigmoid(g1)

// ---------------------------------------------------------------------------
// kernel1 (heterogeneous):
//   blocks [0, 256):    dual GEMM  raw0 = q@W0^T, raw1 = kc@W1^T (compute-bound)
//   blocks [256, 2304): zerofill   out2[b,c,k,:] = 0 where cm*km == 0
//                        (~75% of the 268MB tensor; depends only on masks)
// GEMM hides under the zero store stream.
// ---------------------------------------------------------------------------
__global__ void __launch_bounds__(256, 4) kernel1(
    const float* __restrict__ q, const float* __restrict__ kc,
    const float* __restrict__ W0, const float* __restrict__ W1,
    float* __restrict__ o0, float* __restrict__ o1,
    const int* __restrict__ cmask, const int* __restrict__ kmask,
    float* __restrict__ out2)
{
    const int tid = threadIdx.x;

    if (blockIdx.x < 256) {
        // ---------------- GEMM role ----------------
        const int rem = blockIdx.x & 127;
        const int z   = blockIdx.x >> 7;
        const int n0  = (rem & 3) * 64;
        const int m0  = (rem >> 2) * 64;

        const float* A  = z ? kc : q;
        const float* Bm = z ? W1 : W0;
        float*       C  = z ? o1 : o0;

        __shared__ __align__(16) float As[32][68];
        __shared__ __align__(16) float Bs[32][68];

        const int tx = tid & 15;
        const int ty = tid >> 4;
        const int lr  = tid >> 2;
        const int lcb = (tid & 3) * 8;

        const float* Ap = A  + (long)(m0 + lr) * 256 + lcb;
        const float* Bp = Bm + (long)(n0 + lr) * 256 + lcb;

        float acc[4][4];
#pragma unroll
        for (int i = 0; i < 4; i++)
#pragma unroll
            for (int j = 0; j < 4; j++) acc[i][j] = 0.f;

        float4 a0 = *(const float4*)Ap;
        float4 a1 = *(const float4*)(Ap + 4);
        float4 b0 = *(const float4*)Bp;
        float4 b1 = *(const float4*)(Bp + 4);

        for (int k0 = 0; k0 < 256; k0 += 32) {
            As[lcb+0][lr] = a0.x; As[lcb+1][lr] = a0.y; As[lcb+2][lr] = a0.z; As[lcb+3][lr] = a0.w;
            As[lcb+4][lr] = a1.x; As[lcb+5][lr] = a1.y; As[lcb+6][lr] = a1.z; As[lcb+7][lr] = a1.w;
            Bs[lcb+0][lr] = b0.x; Bs[lcb+1][lr] = b0.y; Bs[lcb+2][lr] = b0.z; Bs[lcb+3][lr] = b0.w;
            Bs[lcb+4][lr] = b1.x; Bs[lcb+5][lr] = b1.y; Bs[lcb+6][lr] = b1.z; Bs[lcb+7][lr] = b1.w;
            __syncthreads();

            if (k0 + 32 < 256) {
                a0 = *(const float4*)(Ap + k0 + 32);
                a1 = *(const float4*)(Ap + k0 + 36);
                b0 = *(const float4*)(Bp + k0 + 32);
                b1 = *(const float4*)(Bp + k0 + 36);
            }

#pragma unroll
            for (int kq = 0; kq < 32; kq++) {
                float4 av = *(const float4*)&As[kq][ty * 4];
                float4 bv = *(const float4*)&Bs[kq][tx * 4];
                acc[0][0] += av.x*bv.x; acc[0][1] += av.x*bv.y; acc[0][2] += av.x*bv.z; acc[0][3] += av.x*bv.w;
                acc[1][0] += av.y*bv.x; acc[1][1] += av.y*bv.y; acc[1][2] += av.y*bv.z; acc[1][3] += av.y*bv.w;
                acc[2][0] += av.z*bv.x; acc[2][1] += av.z*bv.y; acc[2][2] += av.z*bv.z; acc[2][3] += av.z*bv.w;
                acc[3][0] += av.w*bv.x; acc[3][1] += av.w*bv.y; acc[3][2] += av.w*bv.z; acc[3][3] += av.w*bv.w;
            }
            __syncthreads();
        }

#pragma unroll
        for (int i = 0; i < 4; i++) {
            float4 r = make_float4(acc[i][0], acc[i][1], acc[i][2], acc[i][3]);
            *(float4*)&C[(long)(m0 + ty*4 + i) * 256 + n0 + tx*4] = r;
        }
        return;
    }

    // ---------------- zerofill role ----------------
    const int zb = blockIdx.x - 256;     // 0..2047
    const int b  = zb >> 7;
    const int c  = zb & 127;

    __shared__ int skm[PK];
    if (tid < PK) skm[tid] = kmask[b * PK + tid];
    __syncthreads();

    const int cm = cmask[b * PC + c];
    const int dq = tid & 63;
    const int ks = tid >> 6;
    float4* o2 = (float4*)(out2 + (long)(b * PC + c) * KD) + dq;
    const float4 z4 = make_float4(0.f, 0.f, 0.f, 0.f);

    if (cm == 0) {
        for (int k = ks; k < PK; k += 4)
            __stcs(&o2[k * 64], z4);
    } else {
        for (int k = ks; k < PK; k += 4)
            if (skm[k] == 0)
                __stcs(&o2[k * 64], z4);
    }
}

// ---------------------------------------------------------------------------
// bn_merged: 1 block per channel (256: [0..127]=bn0/s0, [128..255]=bn1/s1,t1)
// Computes stats, then applies BN+sigmoid for that channel in one kernel.
// ---------------------------------------------------------------------------
__global__ void bn_merged(const float* __restrict__ gamma0, const float* __restrict__ beta0,
                          const float* __restrict__ gamma1, const float* __restrict__ beta1,
                          const float* __restrict__ kc)
{
    const int cb = blockIdx.x;
    const int c  = cb & 127;
    const int is1 = (cb >> 7);
    const float* src = is1 ? g_raw1 : g_raw0;
    const int t = threadIdx.x;            // t == d

    float s = 0.f, ss = 0.f;
    const float* p = src + c * PD + t;
#pragma unroll
    for (int b = 0; b < PB; b++) {
        float v = p[b * CD];
        s += v; ss += v * v;
    }

    __shared__ float sh[256], sh2[256];
    sh[t] = s; sh2[t] = ss;
    __syncthreads();
    for (int o = 128; o > 0; o >>= 1) {
        if (t < o) { sh[t] += sh[t + o]; sh2[t] += sh2[t + o]; }
        __syncthreads();
    }
    __shared__ float s_sc, s_sf;
    if (t == 0) {
        const float inv_n = 1.f / 4096.f;
        float mean = sh[0] * inv_n;
        float var  = sh2[0] * inv_n - mean * mean;
        float g  = is1 ? gamma1[c] : gamma0[c];
        float be = is1 ? beta1[c]  : beta0[c];
        float sc = g * rsqrtf(var + 1e-5f);
        s_sc = sc;
        s_sf = be - mean * sc;
    }
    __syncthreads();
    const float sc = s_sc, sf = s_sf;

    if (!is1) {
        float* dst = g_s0 + c * PD + t;
#pragma unroll
        for (int b = 0; b < PB; b++) {
            float v = p[b * CD];
            dst[b * CD] = 1.f / (1.f + __expf(-(v * sc + sf)));
        }
    } else {
        float* dsts = g_s1 + c * PD + t;
        float* dstt = g_t1 + c * PD + t;
        const float* kcp = kc + c * PD + t;
#pragma unroll
        for (int b = 0; b < PB; b++) {
            float v = p[b * CD];
            float sv = 1.f / (1.f + __expf(-(v * sc + sf)));
            dsts[b * CD] = sv;
            dstt[b * CD] = kcp[b * CD] * sv;
        }
    }
}

// ---------------------------------------------------------------------------
// kernel3 (heterogeneous):
//   blocks [0, 64): out3 GEMM  -- out3[b] = (1/256) * s0[b] @ s1[b]^T
//   blocks [64, 576): stream nonzero only:
//       out2[b,c,k,d] = t1[b,k,d] * s0[b,c,d]  ONLY where cm*km==1
//       out1[b,c,d]   = tanh( (sum_k ...) / klen[b] )   (always)
// ---------------------------------------------------------------------------
__global__ void __launch_bounds__(256, 4) kernel3(
    const int* __restrict__ cmask, const int* __restrict__ kmask,
    const int* __restrict__ klen,
    float* __restrict__ out1, float* __restrict__ out2, float* __restrict__ out3)
{
    const int tid = threadIdx.x;

    if (blockIdx.x < 64) {
        // ---------------- out3 GEMM role ----------------
        const int idx  = blockIdx.x;
        const int bz   = idx >> 2;
        const int tile = idx & 3;
        const int m0 = (tile >> 1) * 64;
        const int n0 = (tile & 1) * 64;

        const float* Ab = g_s0 + (long)bz * CD;
        const float* Bb = g_s1 + (long)bz * KD;
        float*       Cb = out3 + (long)bz * PC * PK;

        __shared__ __align__(16) float As[16][68];
        __shared__ __align__(16) float Bs[16][68];

        const int tx = tid & 15;
        const int ty = tid >> 4;
        const int kk = tid & 15;
        const int r  = tid >> 4;

        float acc[4][4];
#pragma unroll
        for (int i = 0; i < 4; i++)
#pragma unroll
            for (int j = 0; j < 4; j++) acc[i][j] = 0.f;

        for (int k0 = 0; k0 < 256; k0 += 16) {
#pragma unroll
            for (int p = 0; p < 4; p++) {
                As[kk][r + p*16] = Ab[(long)(m0 + r + p*16) * 256 + k0 + kk];
                Bs[kk][r + p*16] = Bb[(long)(n0 + r + p*16) * 256 + k0 + kk];
            }
            __syncthreads();
#pragma unroll
            for (int kq = 0; kq < 16; kq++) {
                float4 av = *(const float4*)&As[kq][ty * 4];
                float4 bv = *(const float4*)&Bs[kq][tx * 4];
                acc[0][0] += av.x*bv.x; acc[0][1] += av.x*bv.y; acc[0][2] += av.x*bv.z; acc[0][3] += av.x*bv.w;
                acc[1][0] += av.y*bv.x; acc[1][1] += av.y*bv.y; acc[1][2] += av.y*bv.z; acc[1][3] += av.y*bv.w;
                acc[2][0] += av.z*bv.x; acc[2][1] += av.z*bv.y; acc[2][2] += av.z*bv.z; acc[2][3] += av.z*bv.w;
                acc[3][0] += av.w*bv.x; acc[3][1] += av.w*bv.y; acc[3][2] += av.w*bv.z; acc[3][3] += av.w*bv.w;
            }
            __syncthreads();
        }

#pragma unroll
        for (int i = 0; i < 4; i++) {
            const long row = m0 + ty*4 + i;
#pragma unroll
            for (int j = 0; j < 4; j++)
                Cb[row * PK + n0 + tx*4 + j] = acc[i][j] * (1.f / 256.f);
        }
        return;
    }

    // ---------------- stream role (nonzero only) ----------------
    const int sb = blockIdx.x - 64;
    const int c0 = (sb & 31) * 4;
    const int b  = sb >> 5;
    const int dq = tid & 63;
    const int ks = tid >> 6;

    __shared__ int skm[PK];
    if (tid < PK) skm[tid] = kmask[b * PK + tid];

    float4 s0d[4];
    int cm[4];
#pragma unroll
    for (int j = 0; j < 4; j++) {
        s0d[j] = ((const float4*)(g_s0 + (long)(b * PC + c0 + j) * PD))[dq];
        cm[j]  = cmask[b * PC + c0 + j];
    }
    const int anyc = cm[0] | cm[1] | cm[2] | cm[3];
    const float invlen = 1.f / (float)klen[b];
    const float4* t1v = (const float4*)(g_t1 + (long)b * KD) + dq;
    float4* o2 = (float4*)(out2 + (long)(b * PC + c0) * KD) + dq;
    __syncthreads();

    float4 acc[4];
#pragma unroll
    for (int j = 0; j < 4; j++) acc[j] = make_float4(0.f, 0.f, 0.f, 0.f);

    for (int k = ks; k < PK; k += 4) {
        const int m = skm[k] & anyc;
        if (m) {
            float4 t = t1v[k * 64];
#pragma unroll
            for (int j = 0; j < 4; j++) {
                if (m & cm[j]) {
                    float4 v;
                    v.x = t.x * s0d[j].x; v.y = t.y * s0d[j].y;
                    v.z = t.z * s0d[j].z; v.w = t.w * s0d[j].w;
                    acc[j].x += v.x; acc[j].y += v.y; acc[j].z += v.z; acc[j].w += v.w;
                    __stcs(&o2[(long)j * (KD / 4) + k * 64], v);
                }
            }
        }
    }

    __shared__ float4 sh[256];
#pragma unroll
    for (int j = 0; j < 4; j++) {
        __syncthreads();
        sh[tid] = acc[j];
        __syncthreads();
        if (tid < 64) {
            float4 a = sh[tid], b4 = sh[tid + 64], c4 = sh[tid + 128], d4 = sh[tid + 192];
            float4 r;
            r.x = tanhf((a.x + b4.x + c4.x + d4.x) * invlen);
            r.y = tanhf((a.y + b4.y + c4.y + d4.y) * invlen);
            r.z = tanhf((a.z + b4.z + c4.z + d4.z) * invlen);
            r.w = tanhf((a.w + b4.w + c4.w + d4.w) * invlen);
            ((float4*)(out1 + (long)(b * PC + c0 + j) * PD))[tid] = r;
        }
    }
}

// ---------------------------------------------------------------------------
extern "C" void kernel_launch(void* const* d_in, const int* in_sizes, int n_in,
                              void* d_out, int out_size)
{
    const float* q      = (const float*)d_in[0];   // (B,C,D)
    const float* kc     = (const float*)d_in[1];   // (B,K,D)
    const float* W0     = (const float*)d_in[2];   // (D,D)
    const float* W1     = (const float*)d_in[3];   // (D,D)
    const float* bn0_g  = (const float*)d_in[4];
    const float* bn0_b  = (const float*)d_in[5];
    const float* bn1_g  = (const float*)d_in[6];
    const float* bn1_b  = (const float*)d_in[7];
    const int*   cmask  = (const int*)d_in[8];     // (B,C)
    const int*   kmask  = (const int*)d_in[9];     // (B,K)
    const int*   klen   = (const int*)d_in[10];    // (B,)

    float* out  = (float*)d_out;
    float* out1 = out;                                   // (B,C,D)
    float* out2 = out + (long)BCD;                       // (B,C,K,D)
    float* out3 = out + (long)BCD + (long)PB*PC*PK*PD;   // (B,C,K)

    float *raw0, *raw1;
    cudaGetSymbolAddress((void**)&raw0, g_raw0);
    cudaGetSymbolAddress((void**)&raw1, g_raw1);

    // 1) dual GEMM (256 blocks) hidden under mask-zero fill of out2 (2048 blocks)
    kernel1<<<256 + 2048, 256>>>(q, kc, W0, W1, raw0, raw1, cmask, kmask, out2);

    // 2) BN stats + apply + sigmoid + t1, one pass (256 blocks)
    bn_merged<<<256, 256>>>(bn0_g, bn0_b, bn1_g, bn1_b, kc);

    // 3) out3 GEMM (64 blocks) + nonzero stream / out1 (512 blocks)
    kernel3<<<64 + 512, 256>>>(cmask, kmask, klen, out1, out2, out3);
}